// round 2
// baseline (speedup 1.0000x reference)
#include <cuda_runtime.h>
#include <cstdint>

#define NN 10000
#define NE 50000
#define WD 64
#define DEPTH 4
#define K2N 4096   // WD*WD

typedef unsigned long long u64;

// ---- packed fp32x2 helpers (Blackwell FFMA2 path, PTX-only) ----
__device__ __forceinline__ u64 pack2(float x, float y) {
    u64 r; asm("mov.b64 %0, {%1,%2};" : "=l"(r) : "f"(x), "f"(y)); return r;
}
__device__ __forceinline__ void unpack2(u64 v, float& x, float& y) {
    asm("mov.b64 {%0,%1}, %2;" : "=f"(x), "=f"(y) : "l"(v));
}
__device__ __forceinline__ void fma2(u64& d, u64 a, u64 b) {
    asm("fma.rn.f32x2 %0, %1, %2, %0;" : "+l"(d) : "l"(a), "l"(b));
}

// ---- scratch (device globals: allocation-free) ----
__device__ float g_M[(size_t)NN * K2N];    // 163.8 MB per-node transformed features
__device__ float g_t[NE * WD];             // relu(ea@k1+b1), row-major [E,64]
__device__ float g_K2p[WD * K2N];          // permuted k2_W: K2p[i, k*64+o] = K2[k, i*64+o]
__device__ float g_hb[NN * WD];            // h @ b2r  (bias contribution per node)
__device__ float g_h[2][NN * WD];          // ping-pong node features
__device__ float g_agg[NN * WD];           // scatter accumulator
__device__ float g_invd[NN];               // 1/max(indeg,1)
__device__ int   g_cnt[NN];

// ------------------------------------------------------------------
__global__ void k_zero() {
    int i = blockIdx.x * 256 + threadIdx.x;
    if (i < NN * WD) g_agg[i] = 0.f;
    if (i < NN) g_cnt[i] = 0;
}

// t = relu(edge_attr @ k1_W + k1_b), row-major; also in-degree counts
__global__ void k_edge(const float* __restrict__ ea, const int* __restrict__ ei,
                       const float* __restrict__ k1W, const float* __restrict__ k1b) {
    int i = blockIdx.x * 256 + threadIdx.x;
    if (i >= NE * WD) return;
    int e = i >> 6, o = i & 63;
    float a0 = ea[e * 3 + 0], a1 = ea[e * 3 + 1], a2 = ea[e * 3 + 2];
    float t = fmaf(a0, k1W[o], fmaf(a1, k1W[64 + o], fmaf(a2, k1W[128 + o], k1b[o])));
    g_t[i] = t > 0.f ? t : 0.f;
    if (o == 0) atomicAdd(&g_cnt[ei[NE + e]], 1);
}

// h0 = x @ fc1_W + fc1_b; inv_denom from counts
__global__ void k_node(const float* __restrict__ x, const float* __restrict__ W1,
                       const float* __restrict__ b1) {
    int i = blockIdx.x * 256 + threadIdx.x;
    if (i >= NN * WD) return;
    int n = i >> 6, o = i & 63;
    float v = fmaf(x[n * 3 + 0], W1[o],
              fmaf(x[n * 3 + 1], W1[64 + o],
              fmaf(x[n * 3 + 2], W1[128 + o], b1[o])));
    g_h[0][i] = v;
    if (o == 0) { int c = g_cnt[n]; g_invd[n] = 1.0f / (float)(c > 0 ? c : 1); }
}

// K2p[i, k*64+o] = K2[k, i*64+o]   (one-time permutation, 1 MB)
__global__ void k_perm(const float* __restrict__ k2W) {
    int j = blockIdx.x * 256 + threadIdx.x;
    if (j >= WD * K2N) return;
    int i = j >> 12, ko = j & 4095;
    int k = ko >> 6, o = ko & 63;
    g_K2p[j] = k2W[k * K2N + i * 64 + o];
}

// hb[n,o] = sum_i h[n,i] * k2b[i*64+o]
__global__ void k_hb(const float* __restrict__ k2b, int cur) {
    __shared__ float sb[4096];
    __shared__ float shh[4][64];
    int tid = threadIdx.x;
    int n0 = blockIdx.x * 4;
    for (int i = tid; i < 4096; i += 256) sb[i] = k2b[i];
    int nl = tid >> 6, o = tid & 63;
    int n = n0 + nl;                       // NN % 4 == 0
    shh[nl][o] = g_h[cur][n * 64 + o];
    __syncthreads();
    float acc = 0.f;
#pragma unroll
    for (int i = 0; i < 64; i++) acc = fmaf(shh[nl][i], sb[i * 64 + o], acc);
    g_hb[n * 64 + o] = acc;
}

// M = h @ K2p  ([N,64] x [64,4096]) — packed-f32x2 GEMM, B pre-duplicated in smem
#define M_BM 128
#define M_BN 128
#define A_PITCH 136    // 16B-aligned, 4-way fill conflicts only
__global__ void __launch_bounds__(256, 2) k_M(int cur) {
    extern __shared__ float sm[];
    float* sAT = sm;                              // [64][136] transposed h tile
    u64* sBd = (u64*)(sm + 64 * A_PITCH);         // [64][128] duplicated K2p tile
    int n0 = blockIdx.x * M_BM;
    int c0 = blockIdx.y * M_BN;
    int tid = threadIdx.x;
    const float* h = g_h[cur];

    for (int idx = tid; idx < 64 * M_BM; idx += 256) {
        int r = idx >> 6, i = idx & 63;
        int n = n0 + r;
        sAT[i * A_PITCH + r] = (n < NN) ? h[n * 64 + i] : 0.f;
    }
    for (int idx = tid; idx < 64 * M_BN; idx += 256) {
        int k = idx >> 7, c = idx & 127;
        float v = g_K2p[k * K2N + c0 + c];
        sBd[k * 128 + c] = pack2(v, v);
    }
    __syncthreads();

    int tx = tid & 15, ty = tid >> 4;   // 16 x 16 threads; 8 rows x 8 cols each
    u64 acc[4][8];                      // acc[rp][c]: rows (2rp,2rp+1) of col c
#pragma unroll
    for (int rp = 0; rp < 4; rp++)
#pragma unroll
        for (int c = 0; c < 8; c++) acc[rp][c] = 0ull;

    const float* aptr = sAT + ty * 8;
    const u64* bptr = sBd + tx * 4;
#pragma unroll 4
    for (int k = 0; k < 64; k++) {
        float4 a01 = *(const float4*)(aptr + k * A_PITCH);
        float4 a23 = *(const float4*)(aptr + k * A_PITCH + 4);
        u64 ap0 = pack2(a01.x, a01.y), ap1 = pack2(a01.z, a01.w);
        u64 ap2 = pack2(a23.x, a23.y), ap3 = pack2(a23.z, a23.w);
        ulonglong2 b01 = *(const ulonglong2*)(bptr + k * 128);
        ulonglong2 b23 = *(const ulonglong2*)(bptr + k * 128 + 2);
        ulonglong2 b45 = *(const ulonglong2*)(bptr + k * 128 + 64);
        ulonglong2 b67 = *(const ulonglong2*)(bptr + k * 128 + 66);
        u64 b[8] = {b01.x, b01.y, b23.x, b23.y, b45.x, b45.y, b67.x, b67.y};
#pragma unroll
        for (int c = 0; c < 8; c++) {
            fma2(acc[0][c], ap0, b[c]);
            fma2(acc[1][c], ap1, b[c]);
            fma2(acc[2][c], ap2, b[c]);
            fma2(acc[3][c], ap3, b[c]);
        }
    }

#pragma unroll
    for (int rp = 0; rp < 4; rp++) {
        int n = n0 + ty * 8 + 2 * rp;
        if (n >= NN) break;
        float r0[8], r1[8];
#pragma unroll
        for (int c = 0; c < 8; c++) unpack2(acc[rp][c], r0[c], r1[c]);
        float* d0 = g_M + (size_t)n * K2N + c0;
        *(float4*)(d0 + tx * 4)      = make_float4(r0[0], r0[1], r0[2], r0[3]);
        *(float4*)(d0 + 64 + tx * 4) = make_float4(r0[4], r0[5], r0[6], r0[7]);
        if (n + 1 < NN) {
            float* d1 = d0 + K2N;
            *(float4*)(d1 + tx * 4)      = make_float4(r1[0], r1[1], r1[2], r1[3]);
            *(float4*)(d1 + 64 + tx * 4) = make_float4(r1[4], r1[5], r1[6], r1[7]);
        }
    }
}

// msg[e] = M[src]^T(kxo form) t_e + hb[src]; scatter-add into agg[dst]. Warp/edge.
__global__ void k_msg2(const int* __restrict__ ei) {
    int warp = threadIdx.x >> 5, lane = threadIdx.x & 31;
    int e = blockIdx.x * 8 + warp;
    if (e >= NE) return;
    int src = ei[e], dst = ei[NE + e];
    __shared__ float st[8][64];
    st[warp][lane] = g_t[e * 64 + lane];
    st[warp][32 + lane] = g_t[e * 64 + 32 + lane];
    __syncwarp();
    const u64* Mrow = (const u64*)(g_M + (size_t)src * K2N) + lane;
    u64 acc0 = 0ull, acc1 = 0ull;
#pragma unroll
    for (int k = 0; k < 64; k += 2) {
        u64 t0 = pack2(st[warp][k], st[warp][k]);
        u64 t1 = pack2(st[warp][k + 1], st[warp][k + 1]);
        fma2(acc0, t0, Mrow[k * 32]);
        fma2(acc1, t1, Mrow[(k + 1) * 32]);
    }
    float m0, m1, m2, m3;
    unpack2(acc0, m0, m1); unpack2(acc1, m2, m3);
    const float* hb = g_hb + src * 64 + 2 * lane;
    float* ag = g_agg + dst * 64 + 2 * lane;
    atomicAdd(ag, m0 + m2 + hb[0]);
    atomicAdd(ag + 1, m1 + m3 + hb[1]);
}

// h' = relu(agg*invd + h@root + conv_b); re-zero agg for next iter
__global__ void k_update(const float* __restrict__ root, const float* __restrict__ cb, int cur) {
    __shared__ float srt[64 * 64];
    __shared__ float shh[4][64];
    int tid = threadIdx.x;
    int n0 = blockIdx.x * 4;
    for (int i = tid; i < 4096; i += 256) srt[i] = root[i];
    int nl = tid >> 6, o = tid & 63;
    int n = n0 + nl;                       // NN % 4 == 0
    const float* h = g_h[cur];
    shh[nl][o] = h[n * 64 + o];
    __syncthreads();
    float acc = g_agg[n * 64 + o] * g_invd[n];
    g_agg[n * 64 + o] = 0.f;
#pragma unroll
    for (int i = 0; i < 64; i++) acc = fmaf(shh[nl][i], srt[i * 64 + o], acc);
    acc += cb[o];
    g_h[cur ^ 1][n * 64 + o] = acc > 0.f ? acc : 0.f;
}

// out = h @ fc2_W + fc2_b   (warp per node)
__global__ void k_out(const float* __restrict__ w2, const float* __restrict__ b2,
                      float* __restrict__ out, int cur) {
    int warp = threadIdx.x >> 5, lane = threadIdx.x & 31;
    int n = blockIdx.x * 8 + warp;
    if (n >= NN) return;
    const float* h = g_h[cur] + n * 64;
    float s = h[lane] * w2[lane] + h[32 + lane] * w2[32 + lane];
#pragma unroll
    for (int d = 16; d; d >>= 1) s += __shfl_xor_sync(0xffffffff, s, d);
    if (lane == 0) out[n] = s + b2[0];
}

// ------------------------------------------------------------------
extern "C" void kernel_launch(void* const* d_in, const int* in_sizes, int n_in,
                              void* d_out, int out_size) {
    const float* x    = (const float*)d_in[0];
    const int*   ei   = (const int*)  d_in[1];
    const float* ea   = (const float*)d_in[2];
    const float* fc1W = (const float*)d_in[3];
    const float* fc1b = (const float*)d_in[4];
    const float* k1W  = (const float*)d_in[5];
    const float* k1b  = (const float*)d_in[6];
    const float* k2W  = (const float*)d_in[7];
    const float* k2b  = (const float*)d_in[8];
    const float* root = (const float*)d_in[9];
    const float* cb   = (const float*)d_in[10];
    const float* fc2W = (const float*)d_in[11];
    const float* fc2b = (const float*)d_in[12];
    float* out = (float*)d_out;

    const int smemM = 64 * A_PITCH * 4 + 64 * 128 * 8;  // 34816 + 65536 = 100352
    cudaFuncSetAttribute(k_M, cudaFuncAttributeMaxDynamicSharedMemorySize, smemM);

    k_zero<<<(NN * WD + 255) / 256, 256>>>();
    k_edge<<<(NE * WD + 255) / 256, 256>>>(ea, ei, k1W, k1b);
    k_node<<<(NN * WD + 255) / 256, 256>>>(x, fc1W, fc1b);
    k_perm<<<(WD * K2N + 255) / 256, 256>>>(k2W);

    dim3 gM((NN + M_BM - 1) / M_BM, K2N / M_BN);
    int cur = 0;
    for (int d = 0; d < DEPTH; d++) {
        k_hb<<<NN / 4, 256>>>(k2b, cur);
        k_M<<<gM, 256, smemM>>>(cur);
        k_msg2<<<(NE + 7) / 8, 256>>>(ei);
        k_update<<<NN / 4, 256>>>(root, cb, cur);
        cur ^= 1;
    }
    k_out<<<(NN + 7) / 8, 256>>>(fc2W, fc2b, out, cur);
}

// round 4
// speedup vs baseline: 1.2541x; 1.2541x over previous
#include <cuda_runtime.h>
#include <cstdint>

#define NN 10000
#define NE 50000
#define WD 64
#define DEPTH 4
#define KP 4160          // 4096 + 64 bias rows
#define AGG_KS 5
#define AGG_KSPAN 832    // 13 chunks of 64

typedef unsigned long long u64;

// ---- packed fp32x2 helpers (Blackwell FFMA2 path, PTX-only) ----
__device__ __forceinline__ u64 pack2(float x, float y) {
    u64 r; asm("mov.b64 %0, {%1,%2};" : "=l"(r) : "f"(x), "f"(y)); return r;
}
__device__ __forceinline__ void unpack2(u64 v, float& x, float& y) {
    asm("mov.b64 {%0,%1}, %2;" : "=f"(x), "=f"(y) : "l"(v));
}
__device__ __forceinline__ void fma2(u64& d, u64 a, u64 b) {
    asm("fma.rn.f32x2 %0, %1, %2, %0;" : "+l"(d) : "l"(a), "l"(b));
}

// ---- scratch (device globals: allocation-free) ----
__device__ float g_P[(size_t)NN * KP];     // 166.4 MB [P | S] per node
__device__ float g_B2[KP * WD];            // [K2r ; b2r]  (1.06 MB)
__device__ float g_aggp[AGG_KS * NN * WD]; // K-split partial agg
__device__ float g_t[NE * WD];             // relu(ea@k1+b1), edge order
__device__ float g_ts[NE * WD];            // t gathered into dst-sorted order
__device__ float g_h[2][NN * WD];          // ping-pong node features
__device__ float g_invd[NN];
__device__ int   g_cnt[NN];
__device__ int   g_fill[NN];
__device__ int   g_off[NN + 1];
__device__ int   g_es_src[NE];             // src per sorted edge
__device__ int   g_es_eid[NE];             // original edge id per sorted edge

// ------------------------------------------------------------------
__global__ void k_zero() {
    int i = blockIdx.x * 256 + threadIdx.x;
    if (i < NN) { g_cnt[i] = 0; g_fill[i] = 0; }
}

// t = relu(edge_attr @ k1_W + k1_b); in-degree counts
__global__ void k_edge(const float* __restrict__ ea, const int* __restrict__ ei,
                       const float* __restrict__ k1W, const float* __restrict__ k1b) {
    int i = blockIdx.x * 256 + threadIdx.x;
    if (i >= NE * WD) return;
    int e = i >> 6, o = i & 63;
    float a0 = ea[e * 3 + 0], a1 = ea[e * 3 + 1], a2 = ea[e * 3 + 2];
    float t = fmaf(a0, k1W[o], fmaf(a1, k1W[64 + o], fmaf(a2, k1W[128 + o], k1b[o])));
    g_t[i] = t > 0.f ? t : 0.f;
    if (o == 0) atomicAdd(&g_cnt[ei[NE + e]], 1);
}

// h0 = x @ fc1_W + fc1_b; inv_denom (after k_edge)
__global__ void k_node(const float* __restrict__ x, const float* __restrict__ W1,
                       const float* __restrict__ b1) {
    int i = blockIdx.x * 256 + threadIdx.x;
    if (i >= NN * WD) return;
    int n = i >> 6, o = i & 63;
    float v = fmaf(x[n * 3 + 0], W1[o],
              fmaf(x[n * 3 + 1], W1[64 + o],
              fmaf(x[n * 3 + 2], W1[128 + o], b1[o])));
    g_h[0][i] = v;
    if (o == 0) { int c = g_cnt[n]; g_invd[n] = 1.0f / (float)(c > 0 ? c : 1); }
}

// exclusive prefix sum of cnt -> off (single block)
__global__ void k_scan() {
    __shared__ int ss[256];
    int tid = threadIdx.x;
    int base = tid * 40;
    int s = 0;
    for (int q = 0; q < 40; q++) { int idx = base + q; if (idx < NN) s += g_cnt[idx]; }
    ss[tid] = s;
    __syncthreads();
    if (tid == 0) {
        int run = 0;
        for (int i = 0; i < 256; i++) { int v = ss[i]; ss[i] = run; run += v; }
    }
    __syncthreads();
    int run = ss[tid];
    for (int q = 0; q < 40; q++) {
        int idx = base + q;
        if (idx < NN) { g_off[idx] = run; run += g_cnt[idx]; }
    }
    if (tid == 0) g_off[NN] = NE;
}

// counting-sort scatter: edges grouped by dst
__global__ void k_sort(const int* __restrict__ ei) {
    int e = blockIdx.x * 256 + threadIdx.x;
    if (e >= NE) return;
    int src = ei[e], dst = ei[NE + e];
    int pos = g_off[dst] + atomicAdd(&g_fill[dst], 1);
    g_es_src[pos] = src;
    g_es_eid[pos] = e;
}

// ts[j] = t[eid[j]]  (one-time gather so per-iter reads are sequential)
__global__ void k_gather_t() {
    int i = blockIdx.x * 256 + threadIdx.x;
    if (i >= NE * WD) return;
    int j = i >> 6, o = i & 63;
    g_ts[i] = g_t[g_es_eid[j] * 64 + o];
}

// B' = [K2r ; b2r]: B2[i*64+k, o] = k2W[k,i*64+o]; B2[4096+i, o] = k2b[i*64+o]
__global__ void k_perm(const float* __restrict__ k2W, const float* __restrict__ k2b) {
    int j = blockIdx.x * 256 + threadIdx.x;
    if (j >= KP * 64) return;
    int r = j >> 6, o = j & 63;
    if (r < 4096) {
        int i = r >> 6, k = r & 63;
        g_B2[j] = k2W[k * 4096 + i * 64 + o];
    } else {
        g_B2[j] = k2b[(r - 4096) * 64 + o];
    }
}

// P'[n] = [ sum_e h[src]⊗t[e] | sum_e h[src] ]   (block per node, no atomics)
__global__ void k_build(int cur) {
    __shared__ float sh[16][128];
    int n = blockIdx.x;
    int tid = threadIdx.x;
    int start = g_off[n], end = g_off[n + 1];
    float acc[16];
#pragma unroll
    for (int p = 0; p < 16; p++) acc[p] = 0.f;
    float sacc = 0.f;
    const float* __restrict__ h = g_h[cur];
    int i0 = tid >> 6;      // 0..3
    int k = tid & 63;
    for (int base = start; base < end; base += 16) {
        int nb = min(16, end - base);
        __syncthreads();
        for (int idx = tid; idx < nb * 128; idx += 256) {
            int j = idx >> 7, f = idx & 127;
            int jj = base + j;
            if (f < 64) sh[j][f] = h[g_es_src[jj] * 64 + f];
            else        sh[j][f] = g_ts[jj * 64 + f - 64];
        }
        __syncthreads();
        for (int j = 0; j < nb; j++) {
            float tv = sh[j][64 + k];
#pragma unroll
            for (int p = 0; p < 16; p++)
                acc[p] = fmaf(sh[j][p * 4 + i0], tv, acc[p]);   // cell = p*256+tid -> i=p*4+i0
            if (tid < 64) sacc += sh[j][tid];
        }
    }
    float* Pn = g_P + (size_t)n * KP;
#pragma unroll
    for (int p = 0; p < 16; p++) Pn[p * 256 + tid] = acc[p];
    if (tid < 64) Pn[4096 + tid] = sacc;
}

// aggp[ks] = P'[:, krange] @ B2[krange, :]
// 128-row x 64-col tiles, fma2 micro 8x4. A lanes broadcast one row; B lanes
// hold ADJACENT COLUMN PAIRS (this is the round-3 bugfix).
__global__ void __launch_bounds__(256, 3) k_aggM() {
    extern __shared__ float sm[];
    float* sAT = sm;                       // [64][136] transposed P chunk
    u64* sBd = (u64*)(sm + 64 * 136);      // [64][32] column-pair-packed B2 chunk
    int n0 = blockIdx.x * 128;
    int ks = blockIdx.y;
    int k0 = ks * AGG_KSPAN;
    int tid = threadIdx.x;
    int tx = tid & 15, ty = tid >> 4;
    u64 acc[8][2];
#pragma unroll
    for (int r = 0; r < 8; r++) { acc[r][0] = 0ull; acc[r][1] = 0ull; }

    for (int kc = 0; kc < 13; kc++) {
        int kb = k0 + kc * 64;
        __syncthreads();
        for (int idx = tid; idx < 128 * 64; idx += 256) {
            int r = idx >> 6, kk = idx & 63;
            int n = n0 + r;
            sAT[kk * 136 + r] = (n < NN) ? g_P[(size_t)n * KP + kb + kk] : 0.f;
        }
        for (int idx = tid; idx < 64 * 32; idx += 256) {
            int kk = idx >> 5, cp = idx & 31;
            const float* bp = g_B2 + (kb + kk) * 64 + 2 * cp;
            sBd[kk * 32 + cp] = pack2(bp[0], bp[1]);     // two adjacent columns
        }
        __syncthreads();
#pragma unroll 4
        for (int kk = 0; kk < 64; kk++) {
            float4 a0 = *(const float4*)(sAT + kk * 136 + ty * 8);
            float4 a1 = *(const float4*)(sAT + kk * 136 + ty * 8 + 4);
            ulonglong2 b = *(const ulonglong2*)(sBd + kk * 32 + tx * 2);
            // b.x = cols (4tx, 4tx+1), b.y = cols (4tx+2, 4tx+3)
            u64 ap;
            ap = pack2(a0.x, a0.x); fma2(acc[0][0], ap, b.x); fma2(acc[0][1], ap, b.y);
            ap = pack2(a0.y, a0.y); fma2(acc[1][0], ap, b.x); fma2(acc[1][1], ap, b.y);
            ap = pack2(a0.z, a0.z); fma2(acc[2][0], ap, b.x); fma2(acc[2][1], ap, b.y);
            ap = pack2(a0.w, a0.w); fma2(acc[3][0], ap, b.x); fma2(acc[3][1], ap, b.y);
            ap = pack2(a1.x, a1.x); fma2(acc[4][0], ap, b.x); fma2(acc[4][1], ap, b.y);
            ap = pack2(a1.y, a1.y); fma2(acc[5][0], ap, b.x); fma2(acc[5][1], ap, b.y);
            ap = pack2(a1.z, a1.z); fma2(acc[6][0], ap, b.x); fma2(acc[6][1], ap, b.y);
            ap = pack2(a1.w, a1.w); fma2(acc[7][0], ap, b.x); fma2(acc[7][1], ap, b.y);
        }
    }

    float* outp = g_aggp + (size_t)ks * NN * 64;
#pragma unroll
    for (int r = 0; r < 8; r++) {
        int n = n0 + ty * 8 + r;
        if (n < NN) {
            float v0, v1, v2, v3;
            unpack2(acc[r][0], v0, v1);
            unpack2(acc[r][1], v2, v3);
            *(float4*)(outp + n * 64 + tx * 4) = make_float4(v0, v1, v2, v3);
        }
    }
}

// h' = relu(sum(aggp)*invd + h@root + conv_b)
__global__ void k_update(const float* __restrict__ root, const float* __restrict__ cb, int cur) {
    __shared__ float srt[64 * 64];
    __shared__ float shh[4][64];
    int tid = threadIdx.x;
    int n0 = blockIdx.x * 4;
    for (int i = tid; i < 4096; i += 256) srt[i] = root[i];
    int nl = tid >> 6, o = tid & 63;
    int n = n0 + nl;                       // NN % 4 == 0
    const float* h = g_h[cur];
    shh[nl][o] = h[n * 64 + o];
    __syncthreads();
    float acc = 0.f;
#pragma unroll
    for (int s = 0; s < AGG_KS; s++) acc += g_aggp[(size_t)s * NN * 64 + n * 64 + o];
    acc *= g_invd[n];
#pragma unroll
    for (int i = 0; i < 64; i++) acc = fmaf(shh[nl][i], srt[i * 64 + o], acc);
    acc += cb[o];
    g_h[cur ^ 1][n * 64 + o] = acc > 0.f ? acc : 0.f;
}

// out = h @ fc2_W + fc2_b
__global__ void k_out(const float* __restrict__ w2, const float* __restrict__ b2,
                      float* __restrict__ out, int cur) {
    int warp = threadIdx.x >> 5, lane = threadIdx.x & 31;
    int n = blockIdx.x * 8 + warp;
    if (n >= NN) return;
    const float* h = g_h[cur] + n * 64;
    float s = h[lane] * w2[lane] + h[32 + lane] * w2[32 + lane];
#pragma unroll
    for (int d = 16; d; d >>= 1) s += __shfl_xor_sync(0xffffffff, s, d);
    if (lane == 0) out[n] = s + b2[0];
}

// ------------------------------------------------------------------
extern "C" void kernel_launch(void* const* d_in, const int* in_sizes, int n_in,
                              void* d_out, int out_size) {
    const float* x    = (const float*)d_in[0];
    const int*   ei   = (const int*)  d_in[1];
    const float* ea   = (const float*)d_in[2];
    const float* fc1W = (const float*)d_in[3];
    const float* fc1b = (const float*)d_in[4];
    const float* k1W  = (const float*)d_in[5];
    const float* k1b  = (const float*)d_in[6];
    const float* k2W  = (const float*)d_in[7];
    const float* k2b  = (const float*)d_in[8];
    const float* root = (const float*)d_in[9];
    const float* cb   = (const float*)d_in[10];
    const float* fc2W = (const float*)d_in[11];
    const float* fc2b = (const float*)d_in[12];
    float* out = (float*)d_out;

    const int smemA = 64 * 136 * 4 + 64 * 32 * 8;   // 34816 + 16384 = 51200
    cudaFuncSetAttribute(k_aggM, cudaFuncAttributeMaxDynamicSharedMemorySize, smemA);

    k_zero<<<(NN + 255) / 256, 256>>>();
    k_edge<<<(NE * WD + 255) / 256, 256>>>(ea, ei, k1W, k1b);
    k_node<<<(NN * WD + 255) / 256, 256>>>(x, fc1W, fc1b);
    k_scan<<<1, 256>>>();
    k_sort<<<(NE + 255) / 256, 256>>>(ei);
    k_gather_t<<<(NE * WD + 255) / 256, 256>>>();
    k_perm<<<(KP * 64 + 255) / 256, 256>>>(k2W, k2b);

    dim3 gagg((NN + 127) / 128, AGG_KS);
    int cur = 0;
    for (int d = 0; d < DEPTH; d++) {
        k_build<<<NN, 256>>>(cur);
        k_aggM<<<gagg, 256, smemA>>>();
        k_update<<<NN / 4, 256>>>(root, cb, cur);
        cur ^= 1;
    }
    k_out<<<(NN + 7) / 8, 256>>>(fc2W, fc2b, out, cur);
}

// round 6
// speedup vs baseline: 1.6861x; 1.3445x over previous
#include <cuda_runtime.h>
#include <cuda_bf16.h>
#include <cstdint>

#define NN 10000
#define NE 50000
#define WD 64
#define DEPTH 4
#define KP2 4224          // 4096 (P) + 64 (S/bias) + 64 (h/root)
#define NROWS 10112       // 79 * 128, padded
#define KSPLIT 2
#define KHALF 2112        // KP2 / 2
#define KSTEPS 66         // KHALF / 32

typedef unsigned long long u64;

// ================= mma.sync / ldmatrix helpers (sm_80+, target-portable) ====
__device__ __forceinline__ uint32_t s2u(const void* p) {
    uint32_t a;
    asm("{ .reg .u64 t; cvta.to.shared.u64 t, %1; cvt.u32.u64 %0, t; }" : "=r"(a) : "l"(p));
    return a;
}
__device__ __forceinline__ void ldsm4(uint32_t* r, uint32_t addr) {
    asm volatile("ldmatrix.sync.aligned.m8n8.x4.shared.b16 {%0,%1,%2,%3}, [%4];"
        : "=r"(r[0]), "=r"(r[1]), "=r"(r[2]), "=r"(r[3]) : "r"(addr));
}
__device__ __forceinline__ void mma16816(float* c, const uint32_t* a, const uint32_t* b) {
    asm volatile(
        "mma.sync.aligned.m16n8k16.row.col.f32.bf16.bf16.f32 "
        "{%0,%1,%2,%3}, {%4,%5,%6,%7}, {%8,%9}, {%0,%1,%2,%3};"
        : "+f"(c[0]), "+f"(c[1]), "+f"(c[2]), "+f"(c[3])
        : "r"(a[0]), "r"(a[1]), "r"(a[2]), "r"(a[3]), "r"(b[0]), "r"(b[1]));
}

// ================= scratch =================================================
__device__ __nv_bfloat16 g_Ah[(size_t)NROWS * KP2];   // 85.4 MB
__device__ __nv_bfloat16 g_Al[(size_t)NROWS * KP2];   // 85.4 MB
__device__ __nv_bfloat16 g_Bh[WD * KP2];              // B^T [o][k], 528 KB
__device__ __nv_bfloat16 g_Bl[WD * KP2];
__device__ float g_aggp[KSPLIT * NN * WD];            // K-split partials
__device__ float g_ts[NE * WD];                       // t, dst-sorted order
__device__ float g_t[NE * WD];
__device__ float g_h[2][NN * WD];
__device__ float g_invd[NN];
__device__ int   g_cnt[NN];
__device__ int   g_fill[NN];
__device__ int   g_off[NN + 1];
__device__ int   g_es_src[NE];
__device__ int   g_es_eid[NE];

__device__ __forceinline__ void split_bf16(float v, __nv_bfloat16& hi, __nv_bfloat16& lo) {
    hi = __float2bfloat16(v);
    lo = __float2bfloat16(v - __bfloat162float(hi));
}

// ================= setup kernels ===========================================
__global__ void k_zero() {
    int i = blockIdx.x * 256 + threadIdx.x;
    if (i < NN) { g_cnt[i] = 0; g_fill[i] = 0; }
}

__global__ void k_padzero() {   // zero pad rows NN..NROWS of A arrays
    int i = blockIdx.x * 256 + threadIdx.x;
    int total = (NROWS - NN) * KP2;
    if (i < total) {
        size_t base = (size_t)NN * KP2 + i;
        g_Ah[base] = __float2bfloat16(0.f);
        g_Al[base] = __float2bfloat16(0.f);
    }
}

__global__ void k_edge(const float* __restrict__ ea, const int* __restrict__ ei,
                       const float* __restrict__ k1W, const float* __restrict__ k1b) {
    int i = blockIdx.x * 256 + threadIdx.x;
    if (i >= NE * WD) return;
    int e = i >> 6, o = i & 63;
    float a0 = ea[e * 3 + 0], a1 = ea[e * 3 + 1], a2 = ea[e * 3 + 2];
    float t = fmaf(a0, k1W[o], fmaf(a1, k1W[64 + o], fmaf(a2, k1W[128 + o], k1b[o])));
    g_t[i] = t > 0.f ? t : 0.f;
    if (o == 0) atomicAdd(&g_cnt[ei[NE + e]], 1);
}

__global__ void k_node(const float* __restrict__ x, const float* __restrict__ W1,
                       const float* __restrict__ b1) {
    int i = blockIdx.x * 256 + threadIdx.x;
    if (i >= NN * WD) return;
    int n = i >> 6, o = i & 63;
    float v = fmaf(x[n * 3 + 0], W1[o],
              fmaf(x[n * 3 + 1], W1[64 + o],
              fmaf(x[n * 3 + 2], W1[128 + o], b1[o])));
    g_h[0][i] = v;
    if (o == 0) { int c = g_cnt[n]; g_invd[n] = 1.0f / (float)(c > 0 ? c : 1); }
}

__global__ void k_scan() {
    __shared__ int ss[256];
    __shared__ int ws[8];
    int tid = threadIdx.x;
    int base = tid * 40;
    int s = 0;
    for (int q = 0; q < 40; q++) { int idx = base + q; if (idx < NN) s += g_cnt[idx]; }
    int lane = tid & 31, wrp = tid >> 5;
    int v = s;
#pragma unroll
    for (int d = 1; d < 32; d <<= 1) {
        int o = __shfl_up_sync(0xffffffff, v, d);
        if (lane >= d) v += o;
    }
    if (lane == 31) ws[wrp] = v;
    ss[tid] = v - s;
    __syncthreads();
    if (tid == 0) {
        int run = 0;
        for (int w = 0; w < 8; w++) { int t = ws[w]; ws[w] = run; run += t; }
    }
    __syncthreads();
    int run = ss[tid] + ws[wrp];
    for (int q = 0; q < 40; q++) {
        int idx = base + q;
        if (idx < NN) { g_off[idx] = run; run += g_cnt[idx]; }
    }
    if (tid == 0) g_off[NN] = NE;
}

__global__ void k_sort(const int* __restrict__ ei) {
    int e = blockIdx.x * 256 + threadIdx.x;
    if (e >= NE) return;
    int src = ei[e], dst = ei[NE + e];
    int pos = g_off[dst] + atomicAdd(&g_fill[dst], 1);
    g_es_src[pos] = src;
    g_es_eid[pos] = e;
}

__global__ void k_gather_t() {
    int i = blockIdx.x * 256 + threadIdx.x;
    if (i >= NE * WD) return;
    int j = i >> 6, o = i & 63;
    g_ts[i] = g_t[g_es_eid[j] * 64 + o];
}

// B^T[o][k]: k<4096 -> k2W[(k&63)*4096 + (k>>6)*64 + o]; 4096..4159 -> k2b;
// 4160..4223 -> root. bf16 hi/lo.
__global__ void k_permB(const float* __restrict__ k2W, const float* __restrict__ k2b,
                        const float* __restrict__ root) {
    int j = blockIdx.x * 256 + threadIdx.x;
    if (j >= WD * KP2) return;
    int o = j / KP2, k = j % KP2;
    float v;
    if (k < 4096) {
        int i = k >> 6, kq = k & 63;
        v = k2W[kq * 4096 + i * 64 + o];
    } else if (k < 4160) {
        v = k2b[(k - 4096) * 64 + o];
    } else {
        v = root[(k - 4160) * 64 + o];
    }
    __nv_bfloat16 hi, lo;
    split_bf16(v, hi, lo);
    g_Bh[j] = hi;
    g_Bl[j] = lo;
}

// ================= per-iteration kernels ===================================
// A row n = [ invd*(sum_e h_src ⊗ t_e) | invd*(sum_e h_src) | h_n ], bf16 split
__global__ void k_build(int cur) {
    __shared__ float sh[16][128];
    int n = blockIdx.x;
    int tid = threadIdx.x;
    int start = g_off[n], end = g_off[n + 1];
    float acc[16];
#pragma unroll
    for (int p = 0; p < 16; p++) acc[p] = 0.f;
    float sacc = 0.f;
    const float* __restrict__ h = g_h[cur];
    int i0 = tid >> 6;
    int k = tid & 63;
    for (int base = start; base < end; base += 16) {
        int nb = min(16, end - base);
        __syncthreads();
        for (int idx = tid; idx < nb * 128; idx += 256) {
            int j = idx >> 7, f = idx & 127;
            int jj = base + j;
            if (f < 64) sh[j][f] = h[g_es_src[jj] * 64 + f];
            else        sh[j][f] = g_ts[jj * 64 + f - 64];
        }
        __syncthreads();
        for (int j = 0; j < nb; j++) {
            float tv = sh[j][64 + k];
#pragma unroll
            for (int p = 0; p < 16; p++)
                acc[p] = fmaf(sh[j][p * 4 + i0], tv, acc[p]);
            if (tid < 64) sacc += sh[j][tid];
        }
    }
    float inv = g_invd[n];
    __nv_bfloat16* Ah = g_Ah + (size_t)n * KP2;
    __nv_bfloat16* Al = g_Al + (size_t)n * KP2;
#pragma unroll
    for (int p = 0; p < 16; p++) {
        __nv_bfloat16 hi, lo;
        split_bf16(acc[p] * inv, hi, lo);
        Ah[p * 256 + tid] = hi;
        Al[p * 256 + tid] = lo;
    }
    if (tid < 64) {
        __nv_bfloat16 hi, lo;
        split_bf16(sacc * inv, hi, lo);
        Ah[4096 + tid] = hi;
        Al[4096 + tid] = lo;
        split_bf16(h[n * 64 + tid], hi, lo);
        Ah[4160 + tid] = hi;
        Al[4160 + tid] = lo;
    }
}

// mma.sync bf16-split GEMM: aggp[ks][n0:n0+128, 0:64] = A[., krange] @ B[krange]^T
// 8 warps x (16 rows x 64 cols). K-step 32. 3-term split per k-frag.
#define APITCH 40   // bf16 elems per smem row (32 + 8 pad -> 80 bytes)
__global__ void __launch_bounds__(256) k_gemm() {
    __shared__ __nv_bfloat16 sAh[128 * APITCH];
    __shared__ __nv_bfloat16 sAl[128 * APITCH];
    __shared__ __nv_bfloat16 sBh[64 * APITCH];
    __shared__ __nv_bfloat16 sBl[64 * APITCH];

    int tid = threadIdx.x;
    int warp = tid >> 5, lane = tid & 31;
    int n0 = blockIdx.x * 128;
    int ks = blockIdx.y;
    int wm = warp * 16;

    uint32_t uAh = s2u(sAh), uAl = s2u(sAl), uBh = s2u(sBh), uBl = s2u(sBl);

    float c[8][4];
#pragma unroll
    for (int f = 0; f < 8; f++)
#pragma unroll
        for (int q = 0; q < 4; q++) c[f][q] = 0.f;

    // fill indices
    int ar0 = tid >> 2, au0 = tid & 3;            // A: 2 units per thread
    int br = tid >> 2, bu = tid & 3;              // B: 1 unit per thread (tid<256 covers 64*4)

    // ldmatrix addresses (byte offsets within tiles)
    uint32_t aoff = (uint32_t)(wm + (lane & 15)) * (APITCH * 2) + ((lane >> 4) * 16);
    uint32_t boffBase = (uint32_t)((lane & 7) + ((lane >> 4) & 1) * 8) * (APITCH * 2)
                      + (((lane >> 3) & 1) * 16);

    int kb = ks * KHALF;
    for (int step = 0; step < KSTEPS; step++, kb += 32) {
        __syncthreads();
        // A tiles: 128 rows x 64B
        {
            size_t g0 = (size_t)(n0 + ar0) * KP2 + kb + au0 * 8;
            *(uint4*)(sAh + ar0 * APITCH + au0 * 8) = *(const uint4*)(g_Ah + g0);
            *(uint4*)(sAl + ar0 * APITCH + au0 * 8) = *(const uint4*)(g_Al + g0);
            size_t g1 = (size_t)(n0 + 64 + ar0) * KP2 + kb + au0 * 8;
            *(uint4*)(sAh + (64 + ar0) * APITCH + au0 * 8) = *(const uint4*)(g_Ah + g1);
            *(uint4*)(sAl + (64 + ar0) * APITCH + au0 * 8) = *(const uint4*)(g_Al + g1);
        }
        // B tiles: 64 rows x 64B
        {
            size_t g0 = (size_t)br * KP2 + kb + bu * 8;
            *(uint4*)(sBh + br * APITCH + bu * 8) = *(const uint4*)(g_Bh + g0);
            *(uint4*)(sBl + br * APITCH + bu * 8) = *(const uint4*)(g_Bl + g0);
        }
        __syncthreads();

#pragma unroll
        for (int kf = 0; kf < 2; kf++) {
            uint32_t koff = kf * 32;   // 16 bf16 = 32 bytes
            uint32_t ah[4], al[4];
            ldsm4(ah, uAh + aoff + koff);
            ldsm4(al, uAl + aoff + koff);
#pragma unroll
            for (int ng = 0; ng < 4; ng++) {
                uint32_t rowoff = (uint32_t)(ng * 16) * (APITCH * 2);
                uint32_t bh[4], bl[4];
                ldsm4(bh, uBh + boffBase + rowoff + koff);
                ldsm4(bl, uBl + boffBase + rowoff + koff);
                // half 0: b regs (0,1); half 1: (2,3)
                mma16816(c[ng * 2 + 0], ah, bh + 0);
                mma16816(c[ng * 2 + 0], al, bh + 0);   // wait: al x bh uses SAME acc? yes accumulate
                mma16816(c[ng * 2 + 1], ah, bh + 2);
                mma16816(c[ng * 2 + 1], al, bh + 2);
                mma16816(c[ng * 2 + 0], ah, bl + 0);
                mma16816(c[ng * 2 + 1], ah, bl + 2);
            }
        }
    }

    // epilogue: c[f][0..3] -> rows (wm + lane/4, +8), cols ng*16 + half*8 + (lane&3)*2
    float* outp = g_aggp + (size_t)ks * NN * 64;
#pragma unroll
    for (int f = 0; f < 8; f++) {
        int ng = f >> 1, half = f & 1;
        int col = ng * 16 + half * 8 + (lane & 3) * 2;
        int r0 = n0 + wm + (lane >> 2);
        if (r0 < NN) *(float2*)(outp + r0 * 64 + col) = make_float2(c[f][0], c[f][1]);
        int r1 = r0 + 8;
        if (r1 < NN) *(float2*)(outp + r1 * 64 + col) = make_float2(c[f][2], c[f][3]);
    }
}

// h' = relu(part0 + part1 + conv_b)
__global__ void k_comb(const float* __restrict__ cb, int nxt) {
    int i = blockIdx.x * 256 + threadIdx.x;
    if (i >= NN * 64) return;
    int o = i & 63;
    float v = g_aggp[i] + g_aggp[NN * 64 + i] + cb[o];
    g_h[nxt][i] = v > 0.f ? v : 0.f;
}

__global__ void k_out(const float* __restrict__ w2, const float* __restrict__ b2,
                      float* __restrict__ out, int cur) {
    int warp = threadIdx.x >> 5, lane = threadIdx.x & 31;
    int n = blockIdx.x * 8 + warp;
    if (n >= NN) return;
    const float* h = g_h[cur] + n * 64;
    float s = h[lane] * w2[lane] + h[32 + lane] * w2[32 + lane];
#pragma unroll
    for (int d = 16; d; d >>= 1) s += __shfl_xor_sync(0xffffffff, s, d);
    if (lane == 0) out[n] = s + b2[0];
}

// ================= launch ==================================================
extern "C" void kernel_launch(void* const* d_in, const int* in_sizes, int n_in,
                              void* d_out, int out_size) {
    const float* x    = (const float*)d_in[0];
    const int*   ei   = (const int*)  d_in[1];
    const float* ea   = (const float*)d_in[2];
    const float* fc1W = (const float*)d_in[3];
    const float* fc1b = (const float*)d_in[4];
    const float* k1W  = (const float*)d_in[5];
    const float* k1b  = (const float*)d_in[6];
    const float* k2W  = (const float*)d_in[7];
    const float* k2b  = (const float*)d_in[8];
    const float* root = (const float*)d_in[9];
    const float* cb   = (const float*)d_in[10];
    const float* fc2W = (const float*)d_in[11];
    const float* fc2b = (const float*)d_in[12];
    float* out = (float*)d_out;

    k_zero<<<(NN + 255) / 256, 256>>>();
    k_padzero<<<((NROWS - NN) * KP2 + 255) / 256, 256>>>();
    k_edge<<<(NE * WD + 255) / 256, 256>>>(ea, ei, k1W, k1b);
    k_node<<<(NN * WD + 255) / 256, 256>>>(x, fc1W, fc1b);
    k_scan<<<1, 256>>>();
    k_sort<<<(NE + 255) / 256, 256>>>(ei);
    k_gather_t<<<(NE * WD + 255) / 256, 256>>>();
    k_permB<<<(WD * KP2 + 255) / 256, 256>>>(k2W, k2b, root);

    dim3 gg(NROWS / 128, KSPLIT);
    int cur = 0;
    for (int d = 0; d < DEPTH; d++) {
        k_build<<<NN, 256>>>(cur);
        k_gemm<<<gg, 256>>>();
        k_comb<<<(NN * 64 + 255) / 256, 256>>>(cb, cur ^ 1);
        cur ^= 1;
    }
    k_out<<<(NN + 7) / 8, 256>>>(fc2W, fc2b, out, cur);
}

// round 7
// speedup vs baseline: 1.7348x; 1.0288x over previous
#include <cuda_runtime.h>
#include <cuda_bf16.h>
#include <cstdint>

#define NN 10000
#define NE 50000
#define WD 64
#define DEPTH 4
#define KP2 4224          // 4096 (P) + 64 (S/bias) + 64 (h/root)
#define NROWS 10112       // 158 * 64, padded
#define KSPLIT 4
#define KQ 1056           // KP2 / 4
#define KSTEPS 33         // KQ / 32

typedef unsigned long long u64;

// ================= mma.sync / ldmatrix helpers (sm_80+, target-portable) ====
__device__ __forceinline__ uint32_t s2u(const void* p) {
    uint32_t a;
    asm("{ .reg .u64 t; cvta.to.shared.u64 t, %1; cvt.u32.u64 %0, t; }" : "=r"(a) : "l"(p));
    return a;
}
__device__ __forceinline__ void ldsm4(uint32_t* r, uint32_t addr) {
    asm volatile("ldmatrix.sync.aligned.m8n8.x4.shared.b16 {%0,%1,%2,%3}, [%4];"
        : "=r"(r[0]), "=r"(r[1]), "=r"(r[2]), "=r"(r[3]) : "r"(addr));
}
__device__ __forceinline__ void mma16816(float* c, const uint32_t* a, const uint32_t* b) {
    asm volatile(
        "mma.sync.aligned.m16n8k16.row.col.f32.bf16.bf16.f32 "
        "{%0,%1,%2,%3}, {%4,%5,%6,%7}, {%8,%9}, {%0,%1,%2,%3};"
        : "+f"(c[0]), "+f"(c[1]), "+f"(c[2]), "+f"(c[3])
        : "r"(a[0]), "r"(a[1]), "r"(a[2]), "r"(a[3]), "r"(b[0]), "r"(b[1]));
}

// ================= scratch =================================================
__device__ __nv_bfloat16 g_Ah[(size_t)NROWS * KP2];   // 85.4 MB
__device__ __nv_bfloat16 g_Al[(size_t)NROWS * KP2];   // 85.4 MB
__device__ __nv_bfloat16 g_Bh[WD * KP2];              // B^T [o][k], 528 KB
__device__ __nv_bfloat16 g_Bl[WD * KP2];
__device__ float g_aggp[KSPLIT * NN * WD];            // K-split partials
__device__ float g_ts[NE * WD];                       // t, dst-sorted order
__device__ float g_t[NE * WD];
__device__ float g_h[2][NN * WD];
__device__ float g_invd[NN];
__device__ int   g_cnt[NN];
__device__ int   g_fill[NN];
__device__ int   g_off[NN + 1];
__device__ int   g_es_src[NE];
__device__ int   g_es_eid[NE];

__device__ __forceinline__ void split_bf16(float v, __nv_bfloat16& hi, __nv_bfloat16& lo) {
    hi = __float2bfloat16(v);
    lo = __float2bfloat16(v - __bfloat162float(hi));
}

// ================= setup kernels ===========================================
__global__ void k_zero() {
    int i = blockIdx.x * 256 + threadIdx.x;
    if (i < NN) { g_cnt[i] = 0; g_fill[i] = 0; }
}

__global__ void k_padzero() {   // zero pad rows NN..NROWS of A arrays
    int i = blockIdx.x * 256 + threadIdx.x;
    int total = (NROWS - NN) * KP2;
    if (i < total) {
        size_t base = (size_t)NN * KP2 + i;
        g_Ah[base] = __float2bfloat16(0.f);
        g_Al[base] = __float2bfloat16(0.f);
    }
}

__global__ void k_edge(const float* __restrict__ ea, const int* __restrict__ ei,
                       const float* __restrict__ k1W, const float* __restrict__ k1b) {
    int i = blockIdx.x * 256 + threadIdx.x;
    if (i >= NE * WD) return;
    int e = i >> 6, o = i & 63;
    float a0 = ea[e * 3 + 0], a1 = ea[e * 3 + 1], a2 = ea[e * 3 + 2];
    float t = fmaf(a0, k1W[o], fmaf(a1, k1W[64 + o], fmaf(a2, k1W[128 + o], k1b[o])));
    g_t[i] = t > 0.f ? t : 0.f;
    if (o == 0) atomicAdd(&g_cnt[ei[NE + e]], 1);
}

__global__ void k_node(const float* __restrict__ x, const float* __restrict__ W1,
                       const float* __restrict__ b1) {
    int i = blockIdx.x * 256 + threadIdx.x;
    if (i >= NN * WD) return;
    int n = i >> 6, o = i & 63;
    float v = fmaf(x[n * 3 + 0], W1[o],
              fmaf(x[n * 3 + 1], W1[64 + o],
              fmaf(x[n * 3 + 2], W1[128 + o], b1[o])));
    g_h[0][i] = v;
    if (o == 0) { int c = g_cnt[n]; g_invd[n] = 1.0f / (float)(c > 0 ? c : 1); }
}

__global__ void k_scan() {
    __shared__ int ss[256];
    __shared__ int ws[8];
    int tid = threadIdx.x;
    int base = tid * 40;
    int s = 0;
    for (int q = 0; q < 40; q++) { int idx = base + q; if (idx < NN) s += g_cnt[idx]; }
    int lane = tid & 31, wrp = tid >> 5;
    int v = s;
#pragma unroll
    for (int d = 1; d < 32; d <<= 1) {
        int o = __shfl_up_sync(0xffffffff, v, d);
        if (lane >= d) v += o;
    }
    if (lane == 31) ws[wrp] = v;
    ss[tid] = v - s;
    __syncthreads();
    if (tid == 0) {
        int run = 0;
        for (int w = 0; w < 8; w++) { int t = ws[w]; ws[w] = run; run += t; }
    }
    __syncthreads();
    int run = ss[tid] + ws[wrp];
    for (int q = 0; q < 40; q++) {
        int idx = base + q;
        if (idx < NN) { g_off[idx] = run; run += g_cnt[idx]; }
    }
    if (tid == 0) g_off[NN] = NE;
}

__global__ void k_sort(const int* __restrict__ ei) {
    int e = blockIdx.x * 256 + threadIdx.x;
    if (e >= NE) return;
    int src = ei[e], dst = ei[NE + e];
    int pos = g_off[dst] + atomicAdd(&g_fill[dst], 1);
    g_es_src[pos] = src;
    g_es_eid[pos] = e;
}

__global__ void k_gather_t() {
    int i = blockIdx.x * 256 + threadIdx.x;
    if (i >= NE * WD) return;
    int j = i >> 6, o = i & 63;
    g_ts[i] = g_t[g_es_eid[j] * 64 + o];
}

// B^T[o][k]: k<4096 -> k2W[(k&63)*4096 + (k>>6)*64 + o]; 4096..4159 -> k2b;
// 4160..4223 -> root. bf16 hi/lo.
__global__ void k_permB(const float* __restrict__ k2W, const float* __restrict__ k2b,
                        const float* __restrict__ root) {
    int j = blockIdx.x * 256 + threadIdx.x;
    if (j >= WD * KP2) return;
    int o = j / KP2, k = j % KP2;
    float v;
    if (k < 4096) {
        int i = k >> 6, kq = k & 63;
        v = k2W[kq * 4096 + i * 64 + o];
    } else if (k < 4160) {
        v = k2b[(k - 4096) * 64 + o];
    } else {
        v = root[(k - 4160) * 64 + o];
    }
    __nv_bfloat16 hi, lo;
    split_bf16(v, hi, lo);
    g_Bh[j] = hi;
    g_Bl[j] = lo;
}

// ================= per-iteration kernels ===================================
// A row n = [ invd*(sum_e h_src ⊗ t_e) | invd*(sum_e h_src) | h_n ], bf16 split.
// Thread owns (i = tid>>2, k = (tid&3)*16 + [0,16)): per edge 1 bcast LDS +
// 4x LDS.128 + 16 FMA; epilogue 2x STG.128 per array.
__global__ void k_build(int cur) {
    __shared__ float sh[16][128];
    int n = blockIdx.x;
    int tid = threadIdx.x;
    int start = g_off[n], end = g_off[n + 1];
    int i = tid >> 2, q = tid & 3;
    float acc[16];
#pragma unroll
    for (int p = 0; p < 16; p++) acc[p] = 0.f;
    float sacc = 0.f;
    const float* __restrict__ h = g_h[cur];
    for (int base = start; base < end; base += 16) {
        int nb = min(16, end - base);
        __syncthreads();
        for (int idx = tid; idx < nb * 128; idx += 256) {
            int j = idx >> 7, f = idx & 127;
            int jj = base + j;
            if (f < 64) sh[j][f] = h[g_es_src[jj] * 64 + f];
            else        sh[j][f] = g_ts[jj * 64 + f - 64];
        }
        __syncthreads();
        for (int j = 0; j < nb; j++) {
            float hv = sh[j][i];
            const float4* tp = (const float4*)&sh[j][64 + q * 16];
            float4 t0 = tp[0], t1 = tp[1], t2 = tp[2], t3 = tp[3];
            acc[0]  = fmaf(hv, t0.x, acc[0]);  acc[1]  = fmaf(hv, t0.y, acc[1]);
            acc[2]  = fmaf(hv, t0.z, acc[2]);  acc[3]  = fmaf(hv, t0.w, acc[3]);
            acc[4]  = fmaf(hv, t1.x, acc[4]);  acc[5]  = fmaf(hv, t1.y, acc[5]);
            acc[6]  = fmaf(hv, t1.z, acc[6]);  acc[7]  = fmaf(hv, t1.w, acc[7]);
            acc[8]  = fmaf(hv, t2.x, acc[8]);  acc[9]  = fmaf(hv, t2.y, acc[9]);
            acc[10] = fmaf(hv, t2.z, acc[10]); acc[11] = fmaf(hv, t2.w, acc[11]);
            acc[12] = fmaf(hv, t3.x, acc[12]); acc[13] = fmaf(hv, t3.y, acc[13]);
            acc[14] = fmaf(hv, t3.z, acc[14]); acc[15] = fmaf(hv, t3.w, acc[15]);
            if (q == 0) sacc += hv;
        }
    }
    float inv = g_invd[n];
    // 16 contiguous bf16 per thread -> 2x uint4 per array
    __nv_bfloat162 hp[8], lp[8];
#pragma unroll
    for (int u = 0; u < 8; u++) {
        float v0 = acc[2 * u] * inv, v1 = acc[2 * u + 1] * inv;
        hp[u] = __floats2bfloat162_rn(v0, v1);
        float l0 = v0 - __bfloat162float(__low2bfloat16(hp[u]));
        float l1 = v1 - __bfloat162float(__high2bfloat16(hp[u]));
        lp[u] = __floats2bfloat162_rn(l0, l1);
    }
    size_t rowo = (size_t)n * KP2 + i * 64 + q * 16;
    *(uint4*)(g_Ah + rowo)     = *(uint4*)&hp[0];
    *(uint4*)(g_Ah + rowo + 8) = *(uint4*)&hp[4];
    *(uint4*)(g_Al + rowo)     = *(uint4*)&lp[0];
    *(uint4*)(g_Al + rowo + 8) = *(uint4*)&lp[4];
    if (q == 0) {
        size_t tb = (size_t)n * KP2;
        __nv_bfloat16 hi, lo;
        split_bf16(sacc * inv, hi, lo);
        g_Ah[tb + 4096 + i] = hi;
        g_Al[tb + 4096 + i] = lo;
        split_bf16(h[n * 64 + i], hi, lo);
        g_Ah[tb + 4160 + i] = hi;
        g_Al[tb + 4160 + i] = lo;
    }
}

// mma.sync bf16-split GEMM: aggp[ks][n0:n0+64, 0:64] = A[., krange] @ B[krange]^T
// 4 warps x (16 rows x 64 cols). 128 threads, grid 158x4 = 632 blocks (1 wave).
#define APITCH 40   // bf16 elems per smem row (32 + 8 pad -> 80 bytes)
__global__ void __launch_bounds__(128) k_gemm() {
    __shared__ __nv_bfloat16 sAh[64 * APITCH];
    __shared__ __nv_bfloat16 sAl[64 * APITCH];
    __shared__ __nv_bfloat16 sBh[64 * APITCH];
    __shared__ __nv_bfloat16 sBl[64 * APITCH];

    int tid = threadIdx.x;
    int warp = tid >> 5, lane = tid & 31;
    int n0 = blockIdx.x * 64;
    int ks = blockIdx.y;
    int wm = warp * 16;

    uint32_t uAh = s2u(sAh), uAl = s2u(sAl), uBh = s2u(sBh), uBl = s2u(sBl);

    float c[8][4];
#pragma unroll
    for (int f = 0; f < 8; f++)
#pragma unroll
        for (int qq = 0; qq < 4; qq++) c[f][qq] = 0.f;

    uint32_t aoff = (uint32_t)(wm + (lane & 15)) * (APITCH * 2) + ((lane >> 4) * 16);
    uint32_t boffBase = (uint32_t)((lane & 7) + ((lane >> 4) & 1) * 8) * (APITCH * 2)
                      + (((lane >> 3) & 1) * 16);

    int kb = ks * KQ;
    for (int step = 0; step < KSTEPS; step++, kb += 32) {
        __syncthreads();
#pragma unroll
        for (int idx = tid; idx < 256; idx += 128) {
            int r = idx >> 2, u = idx & 3;
            size_t ga = (size_t)(n0 + r) * KP2 + kb + u * 8;
            *(uint4*)(sAh + r * APITCH + u * 8) = *(const uint4*)(g_Ah + ga);
            *(uint4*)(sAl + r * APITCH + u * 8) = *(const uint4*)(g_Al + ga);
            size_t gb = (size_t)r * KP2 + kb + u * 8;
            *(uint4*)(sBh + r * APITCH + u * 8) = *(const uint4*)(g_Bh + gb);
            *(uint4*)(sBl + r * APITCH + u * 8) = *(const uint4*)(g_Bl + gb);
        }
        __syncthreads();

#pragma unroll
        for (int kf = 0; kf < 2; kf++) {
            uint32_t koff = kf * 32;
            uint32_t ah[4], al[4];
            ldsm4(ah, uAh + aoff + koff);
            ldsm4(al, uAl + aoff + koff);
#pragma unroll
            for (int ng = 0; ng < 4; ng++) {
                uint32_t rowoff = (uint32_t)(ng * 16) * (APITCH * 2);
                uint32_t bh[4], bl[4];
                ldsm4(bh, uBh + boffBase + rowoff + koff);
                ldsm4(bl, uBl + boffBase + rowoff + koff);
                mma16816(c[ng * 2 + 0], ah, bh + 0);
                mma16816(c[ng * 2 + 0], al, bh + 0);
                mma16816(c[ng * 2 + 0], ah, bl + 0);
                mma16816(c[ng * 2 + 1], ah, bh + 2);
                mma16816(c[ng * 2 + 1], al, bh + 2);
                mma16816(c[ng * 2 + 1], ah, bl + 2);
            }
        }
    }

    float* outp = g_aggp + (size_t)ks * NN * 64;
#pragma unroll
    for (int f = 0; f < 8; f++) {
        int ng = f >> 1, half = f & 1;
        int col = ng * 16 + half * 8 + (lane & 3) * 2;
        int r0 = n0 + wm + (lane >> 2);
        if (r0 < NN) *(float2*)(outp + r0 * 64 + col) = make_float2(c[f][0], c[f][1]);
        int r1 = r0 + 8;
        if (r1 < NN) *(float2*)(outp + r1 * 64 + col) = make_float2(c[f][2], c[f][3]);
    }
}

// h' = relu(sum of 4 partials + conv_b)
__global__ void k_comb(const float* __restrict__ cb, int nxt) {
    int i = blockIdx.x * 256 + threadIdx.x;
    if (i >= NN * 64) return;
    int o = i & 63;
    float v = g_aggp[i] + g_aggp[NN * 64 + i] + g_aggp[2 * NN * 64 + i]
            + g_aggp[3 * NN * 64 + i] + cb[o];
    g_h[nxt][i] = v > 0.f ? v : 0.f;
}

__global__ void k_out(const float* __restrict__ w2, const float* __restrict__ b2,
                      float* __restrict__ out, int cur) {
    int warp = threadIdx.x >> 5, lane = threadIdx.x & 31;
    int n = blockIdx.x * 8 + warp;
    if (n >= NN) return;
    const float* h = g_h[cur] + n * 64;
    float s = h[lane] * w2[lane] + h[32 + lane] * w2[32 + lane];
#pragma unroll
    for (int d = 16; d; d >>= 1) s += __shfl_xor_sync(0xffffffff, s, d);
    if (lane == 0) out[n] = s + b2[0];
}

// ================= launch ==================================================
extern "C" void kernel_launch(void* const* d_in, const int* in_sizes, int n_in,
                              void* d_out, int out_size) {
    const float* x    = (const float*)d_in[0];
    const int*   ei   = (const int*)  d_in[1];
    const float* ea   = (const float*)d_in[2];
    const float* fc1W = (const float*)d_in[3];
    const float* fc1b = (const float*)d_in[4];
    const float* k1W  = (const float*)d_in[5];
    const float* k1b  = (const float*)d_in[6];
    const float* k2W  = (const float*)d_in[7];
    const float* k2b  = (const float*)d_in[8];
    const float* root = (const float*)d_in[9];
    const float* cb   = (const float*)d_in[10];
    const float* fc2W = (const float*)d_in[11];
    const float* fc2b = (const float*)d_in[12];
    float* out = (float*)d_out;

    k_zero<<<(NN + 255) / 256, 256>>>();
    k_padzero<<<((NROWS - NN) * KP2 + 255) / 256, 256>>>();
    k_edge<<<(NE * WD + 255) / 256, 256>>>(ea, ei, k1W, k1b);
    k_node<<<(NN * WD + 255) / 256, 256>>>(x, fc1W, fc1b);
    k_scan<<<1, 256>>>();
    k_sort<<<(NE + 255) / 256, 256>>>(ei);
    k_gather_t<<<(NE * WD + 255) / 256, 256>>>();
    k_permB<<<(WD * KP2 + 255) / 256, 256>>>(k2W, k2b, root);

    dim3 gg(NROWS / 64, KSPLIT);
    int cur = 0;
    for (int d = 0; d < DEPTH; d++) {
        k_build<<<NN, 256>>>(cur);
        k_gemm<<<gg, 128>>>();
        k_comb<<<(NN * 64 + 255) / 256, 256>>>(cb, cur ^ 1);
        cur ^= 1;
    }
    k_out<<<(NN + 7) / 8, 256>>>(fc2W, fc2b, out, cur);
}